// round 2
// baseline (speedup 1.0000x reference)
#include <cuda_runtime.h>
#include <cuda_bf16.h>
#include <cstdint>

// ---------------------------------------------------------------------------
// Problem constants
// ---------------------------------------------------------------------------
#define B_ 4
#define N_ 4096
#define M_ 4096
#define C_ 512
#define R_ (B_ * N_)                     // 16384 rows
static const long NM_ = (long)N_ * M_;   // 16,777,216 per batch

// ---------------------------------------------------------------------------
// GEMM tiling
// ---------------------------------------------------------------------------
#define BM 128
#define BN 128
#define BK 32
#define STAGES 3
#define ROWB 80                   // padded row bytes: 32 bf16 = 64B + 16B pad
#define TILE_B (128 * ROWB)       // 10240 B per operand tile
#define STAGE_B (4 * TILE_B)      // Ahi, Alo, Bhi, Blo
#define SMEM_B (STAGES * STAGE_B) // 122880 B

__device__ __forceinline__ uint32_t smem_u32(const void* p) {
    uint32_t a;
    asm("{ .reg .u64 t; cvta.to.shared.u64 t, %1; cvt.u32.u64 %0, t; }" : "=r"(a) : "l"(p));
    return a;
}

#define LDSM4(r, addr) \
    asm volatile("ldmatrix.sync.aligned.m8n8.x4.shared.b16 {%0,%1,%2,%3}, [%4];" \
                 : "=r"((r)[0]), "=r"((r)[1]), "=r"((r)[2]), "=r"((r)[3]) : "r"(addr))

#define MMA(dd, aa, b0, b1) \
    asm volatile("mma.sync.aligned.m16n8k16.row.col.f32.bf16.bf16.f32 " \
                 "{%0,%1,%2,%3}, {%4,%5,%6,%7}, {%8,%9}, {%0,%1,%2,%3};" \
                 : "+f"((dd)[0]), "+f"((dd)[1]), "+f"((dd)[2]), "+f"((dd)[3]) \
                 : "r"((aa)[0]), "r"((aa)[1]), "r"((aa)[2]), "r"((aa)[3]), \
                   "r"(b0), "r"(b1))

#define CP16(saddr, gptr) \
    asm volatile("cp.async.cg.shared.global [%0], [%1], 16;" :: "r"(saddr), "l"(gptr))

// ---------------------------------------------------------------------------
// Scratch (__device__ globals; no dynamic allocation allowed)
// ---------------------------------------------------------------------------
__device__ __nv_bfloat16 g_rgb_hi[R_ * C_];
__device__ __nv_bfloat16 g_rgb_lo[R_ * C_];
__device__ __nv_bfloat16 g_dep_hi[R_ * C_];
__device__ __nv_bfloat16 g_dep_lo[R_ * C_];
__device__ __nv_bfloat16 g_wt_hi[3 * C_ * C_];   // W^T for q,k,v: [co][c]
__device__ __nv_bfloat16 g_wt_lo[3 * C_ * C_];
__device__ __nv_bfloat16 g_q_hi[R_ * C_];
__device__ __nv_bfloat16 g_q_lo[R_ * C_];
__device__ __nv_bfloat16 g_k_hi[R_ * C_];
__device__ __nv_bfloat16 g_k_lo[R_ * C_];
__device__ __nv_bfloat16 g_vt_hi[(long)B_ * C_ * M_];   // V^T per batch: [b][c][m]
__device__ __nv_bfloat16 g_vt_lo[(long)B_ * C_ * M_];
__device__ float         g_s[(long)B_ * N_ * M_];       // 256 MB scores scratch
__device__ __nv_bfloat16 g_p_hi[(long)B_ * N_ * M_];    // softmax weights hi/lo
__device__ __nv_bfloat16 g_p_lo[(long)B_ * N_ * M_];

// ---------------------------------------------------------------------------
// Elementwise: fp32 -> (hi, lo) bf16 split
// ---------------------------------------------------------------------------
__global__ void split_kernel(const float* __restrict__ x,
                             __nv_bfloat16* __restrict__ hi,
                             __nv_bfloat16* __restrict__ lo, int n) {
    int i = blockIdx.x * blockDim.x + threadIdx.x;
    if (i < n) {
        float v = x[i];
        __nv_bfloat16 h = __float2bfloat16(v);
        hi[i] = h;
        lo[i] = __float2bfloat16(v - __bfloat162float(h));
    }
}

// W [c][co] -> W^T split [co][c]
__global__ void wsplit_kernel(const float* __restrict__ W,
                              __nv_bfloat16* __restrict__ hi,
                              __nv_bfloat16* __restrict__ lo) {
    int i = blockIdx.x * blockDim.x + threadIdx.x;   // i = co*512 + c
    int co = i >> 9, c = i & 511;
    float v = W[c * C_ + co];
    __nv_bfloat16 h = __float2bfloat16(v);
    hi[i] = h;
    lo[i] = __float2bfloat16(v - __bfloat162float(h));
}

// ---------------------------------------------------------------------------
// bf16x3 GEMM via mma.sync: D[128x128] = sum_k A[rowtile,k] * B[coltile,k]
// Both operands K-major. Modes select epilogue:
//   0: out hi/lo split, row-major [row, C_], +bias[col]
//   1: out hi/lo split, transposed per batch [b][col][m], +bias[col]  (V^T)
//   2: out fp32 * scale, [bz][row][col] ld=M_    (scores)
//   3: out fp32,         [bz][row][col] ld=C_    (final output)
// ---------------------------------------------------------------------------
__global__ void __launch_bounds__(256, 1) gemm_bf16x3(
    const __nv_bfloat16* __restrict__ Ahi, const __nv_bfloat16* __restrict__ Alo,
    const __nv_bfloat16* __restrict__ Bhi, const __nv_bfloat16* __restrict__ Blo,
    int Ktot, long aBatch, long bBatch,
    const float* __restrict__ bias, float outScale, int mode,
    float* __restrict__ outF,
    __nv_bfloat16* __restrict__ outHi, __nv_bfloat16* __restrict__ outLo)
{
    extern __shared__ char smem[];
    const uint32_t sb = smem_u32(smem);
    const int tid = threadIdx.x, lane = tid & 31, wid = tid >> 5;
    const int wm = wid >> 2, wn = wid & 3;          // warp grid 2 x 4
    const int bx = blockIdx.x, by = blockIdx.y, bz = blockIdx.z;

    // ---- cp.async assignment: thread -> (row, 32B half of a 64B row chunk)
    const int lrow = tid >> 1;                       // 0..127
    const int lhalf = tid & 1;                       // 0/1 -> +0B / +32B
    const long aOff = bz * aBatch + (long)(bx * 128 + lrow) * Ktot + lhalf * 16;
    const long bOff = bz * bBatch + (long)(by * 128 + lrow) * Ktot + lhalf * 16;
    const __nv_bfloat16* pAh = Ahi + aOff;
    const __nv_bfloat16* pAl = Alo + aOff;
    const __nv_bfloat16* pBh = Bhi + bOff;
    const __nv_bfloat16* pBl = Blo + bOff;
    const uint32_t sst = sb + (uint32_t)lrow * ROWB + lhalf * 32;

    const int kIters = Ktot / BK;

    auto issue = [&](int kt, int stage) {
        const uint32_t s0 = sst + stage * STAGE_B;
        const int off = kt * BK;
        CP16(s0 + 0 * TILE_B,      pAh + off);
        CP16(s0 + 0 * TILE_B + 16, pAh + off + 8);
        CP16(s0 + 1 * TILE_B,      pAl + off);
        CP16(s0 + 1 * TILE_B + 16, pAl + off + 8);
        CP16(s0 + 2 * TILE_B,      pBh + off);
        CP16(s0 + 2 * TILE_B + 16, pBh + off + 8);
        CP16(s0 + 3 * TILE_B,      pBl + off);
        CP16(s0 + 3 * TILE_B + 16, pBl + off + 8);
    };

    float d[4][4][4];
    #pragma unroll
    for (int i = 0; i < 4; i++)
        #pragma unroll
        for (int j = 0; j < 4; j++)
            #pragma unroll
            for (int e = 0; e < 4; e++) d[i][j][e] = 0.f;

    issue(0, 0);
    asm volatile("cp.async.commit_group;" ::: "memory");
    issue(1, 1);
    asm volatile("cp.async.commit_group;" ::: "memory");

    for (int kt = 0; kt < kIters; kt++) {
        asm volatile("cp.async.wait_group 1;" ::: "memory");
        __syncthreads();
        if (kt + 2 < kIters) issue(kt + 2, (kt + 2) % STAGES);
        asm volatile("cp.async.commit_group;" ::: "memory");

        const uint32_t st = sb + (kt % STAGES) * STAGE_B;
        #pragma unroll
        for (int s = 0; s < 2; s++) {                // two k16 steps per BK=32
            uint32_t ah[4][4], al[4][4], bh[4][2], bl[4][2];
            const uint32_t coff = s * 32 + (lane >> 4) * 16;
            const uint32_t rowA = wm * 64 + (lane & 15);
            #pragma unroll
            for (int mt = 0; mt < 4; mt++) {
                const uint32_t a0 = st + (rowA + mt * 16) * ROWB + coff;
                LDSM4(ah[mt], a0);
                LDSM4(al[mt], a0 + TILE_B);
            }
            const uint32_t rowB = wn * 32 + (lane & 15);
            #pragma unroll
            for (int np = 0; np < 2; np++) {
                const uint32_t b0 = st + 2 * TILE_B + (rowB + np * 16) * ROWB + coff;
                uint32_t r[4];
                LDSM4(r, b0);
                bh[2 * np][0] = r[0]; bh[2 * np][1] = r[2];
                bh[2 * np + 1][0] = r[1]; bh[2 * np + 1][1] = r[3];
                LDSM4(r, b0 + TILE_B);
                bl[2 * np][0] = r[0]; bl[2 * np][1] = r[2];
                bl[2 * np + 1][0] = r[1]; bl[2 * np + 1][1] = r[3];
            }
            #pragma unroll
            for (int mt = 0; mt < 4; mt++)
                #pragma unroll
                for (int nt = 0; nt < 4; nt++)
                    MMA(d[mt][nt], ah[mt], bh[nt][0], bh[nt][1]);   // hi*hi
            #pragma unroll
            for (int mt = 0; mt < 4; mt++)
                #pragma unroll
                for (int nt = 0; nt < 4; nt++)
                    MMA(d[mt][nt], ah[mt], bl[nt][0], bl[nt][1]);   // hi*lo
            #pragma unroll
            for (int mt = 0; mt < 4; mt++)
                #pragma unroll
                for (int nt = 0; nt < 4; nt++)
                    MMA(d[mt][nt], al[mt], bh[nt][0], bh[nt][1]);   // lo*hi
        }
    }

    // ---- epilogue (registers only; no smem dependency)
    const int mbase = bx * 128 + wm * 64;
    const int nbase = by * 128 + wn * 32;
    const int lr = lane >> 2;            // 0..7
    const int lc = (lane & 3) * 2;       // 0,2,4,6

    #pragma unroll
    for (int mt = 0; mt < 4; mt++) {
        #pragma unroll
        for (int nt = 0; nt < 4; nt++) {
            #pragma unroll
            for (int h = 0; h < 2; h++) {
                const int m = mbase + mt * 16 + lr + h * 8;
                const int n = nbase + nt * 8 + lc;
                float v0 = d[mt][nt][h * 2 + 0];
                float v1 = d[mt][nt][h * 2 + 1];
                if (mode == 0) {
                    v0 += bias[n]; v1 += bias[n + 1];
                    __nv_bfloat16 h0 = __float2bfloat16(v0);
                    __nv_bfloat16 h1 = __float2bfloat16(v1);
                    __nv_bfloat162 hv; hv.x = h0; hv.y = h1;
                    __nv_bfloat162 lv;
                    lv.x = __float2bfloat16(v0 - __bfloat162float(h0));
                    lv.y = __float2bfloat16(v1 - __bfloat162float(h1));
                    const long idx = (long)m * C_ + n;
                    *(__nv_bfloat162*)(outHi + idx) = hv;
                    *(__nv_bfloat162*)(outLo + idx) = lv;
                } else if (mode == 1) {
                    v0 += bias[n]; v1 += bias[n + 1];
                    const int b = m >> 12, mm = m & 4095;
                    const long idx = (long)b * ((long)C_ * M_) + (long)n * M_ + mm;
                    __nv_bfloat16 h0 = __float2bfloat16(v0);
                    __nv_bfloat16 h1 = __float2bfloat16(v1);
                    outHi[idx] = h0;
                    outLo[idx] = __float2bfloat16(v0 - __bfloat162float(h0));
                    outHi[idx + M_] = h1;
                    outLo[idx + M_] = __float2bfloat16(v1 - __bfloat162float(h1));
                } else if (mode == 2) {
                    const long idx = (long)bz * NM_ + (long)m * M_ + n;
                    float2 v; v.x = v0 * outScale; v.y = v1 * outScale;
                    *(float2*)(outF + idx) = v;
                } else {
                    const long idx = (long)bz * ((long)N_ * C_) + (long)m * C_ + n;
                    float2 v; v.x = v0; v.y = v1;
                    *(float2*)(outF + idx) = v;
                }
            }
        }
    }
}

// ---------------------------------------------------------------------------
// Softmax over rows of S; writes P split into hi/lo bf16.
// One 256-thread block per (b, n) row of 4096 elements.
// ---------------------------------------------------------------------------
__global__ void __launch_bounds__(256) softmax_kernel(const float* __restrict__ S,
                                                      __nv_bfloat16* __restrict__ Phi,
                                                      __nv_bfloat16* __restrict__ Plo) {
    __shared__ float red[8];
    __shared__ float bc;
    const long row = blockIdx.x;
    const float* s = S + row * M_;
    const int tid = threadIdx.x;

    float v[16];
    float mx = -1e30f;
    #pragma unroll
    for (int i = 0; i < 16; i++) {
        v[i] = s[tid + i * 256];
        mx = fmaxf(mx, v[i]);
    }
    #pragma unroll
    for (int o = 16; o; o >>= 1) mx = fmaxf(mx, __shfl_xor_sync(0xFFFFFFFFu, mx, o));
    if ((tid & 31) == 0) red[tid >> 5] = mx;
    __syncthreads();
    if (tid < 32) {
        float m = (tid < 8) ? red[tid] : -1e30f;
        #pragma unroll
        for (int o = 4; o; o >>= 1) m = fmaxf(m, __shfl_xor_sync(0xFFFFFFFFu, m, o));
        if (tid == 0) bc = m;
    }
    __syncthreads();
    mx = bc;

    float sum = 0.f;
    #pragma unroll
    for (int i = 0; i < 16; i++) {
        v[i] = __expf(v[i] - mx);
        sum += v[i];
    }
    #pragma unroll
    for (int o = 16; o; o >>= 1) sum += __shfl_xor_sync(0xFFFFFFFFu, sum, o);
    __syncthreads();
    if ((tid & 31) == 0) red[tid >> 5] = sum;
    __syncthreads();
    if (tid < 32) {
        float m = (tid < 8) ? red[tid] : 0.f;
        #pragma unroll
        for (int o = 4; o; o >>= 1) m += __shfl_xor_sync(0xFFFFFFFFu, m, o);
        if (tid == 0) bc = m;
    }
    __syncthreads();
    const float inv = 1.0f / bc;

    const long base = row * M_ + tid;
    #pragma unroll
    for (int i = 0; i < 16; i++) {
        float p = v[i] * inv;
        __nv_bfloat16 h = __float2bfloat16(p);
        Phi[base + i * 256] = h;
        Plo[base + i * 256] = __float2bfloat16(p - __bfloat162float(h));
    }
}

// ---------------------------------------------------------------------------
// Host launch
// ---------------------------------------------------------------------------
extern "C" void kernel_launch(void* const* d_in, const int* in_sizes, int n_in,
                              void* d_out, int out_size) {
    (void)in_sizes; (void)n_in; (void)out_size;
    const float* rgb = (const float*)d_in[0];
    const float* dep = (const float*)d_in[1];
    const float* Wq  = (const float*)d_in[2];
    const float* bq  = (const float*)d_in[3];
    const float* Wk  = (const float*)d_in[4];
    const float* bk  = (const float*)d_in[5];
    const float* Wv  = (const float*)d_in[6];
    const float* bv  = (const float*)d_in[7];
    float* out = (float*)d_out;

    void* p;
    __nv_bfloat16 *rgb_hi, *rgb_lo, *dep_hi, *dep_lo, *wt_hi, *wt_lo;
    __nv_bfloat16 *q_hi, *q_lo, *k_hi, *k_lo, *vt_hi, *vt_lo, *p_hi, *p_lo;
    float* s;
    cudaGetSymbolAddress(&p, g_rgb_hi); rgb_hi = (__nv_bfloat16*)p;
    cudaGetSymbolAddress(&p, g_rgb_lo); rgb_lo = (__nv_bfloat16*)p;
    cudaGetSymbolAddress(&p, g_dep_hi); dep_hi = (__nv_bfloat16*)p;
    cudaGetSymbolAddress(&p, g_dep_lo); dep_lo = (__nv_bfloat16*)p;
    cudaGetSymbolAddress(&p, g_wt_hi);  wt_hi  = (__nv_bfloat16*)p;
    cudaGetSymbolAddress(&p, g_wt_lo);  wt_lo  = (__nv_bfloat16*)p;
    cudaGetSymbolAddress(&p, g_q_hi);   q_hi   = (__nv_bfloat16*)p;
    cudaGetSymbolAddress(&p, g_q_lo);   q_lo   = (__nv_bfloat16*)p;
    cudaGetSymbolAddress(&p, g_k_hi);   k_hi   = (__nv_bfloat16*)p;
    cudaGetSymbolAddress(&p, g_k_lo);   k_lo   = (__nv_bfloat16*)p;
    cudaGetSymbolAddress(&p, g_vt_hi);  vt_hi  = (__nv_bfloat16*)p;
    cudaGetSymbolAddress(&p, g_vt_lo);  vt_lo  = (__nv_bfloat16*)p;
    cudaGetSymbolAddress(&p, g_p_hi);   p_hi   = (__nv_bfloat16*)p;
    cudaGetSymbolAddress(&p, g_p_lo);   p_lo   = (__nv_bfloat16*)p;
    cudaGetSymbolAddress(&p, g_s);      s      = (float*)p;

    cudaFuncSetAttribute(gemm_bf16x3, cudaFuncAttributeMaxDynamicSharedMemorySize, SMEM_B);

    const int nIn = R_ * C_;   // 8,388,608
    split_kernel<<<(nIn + 255) / 256, 256>>>(rgb, rgb_hi, rgb_lo, nIn);
    split_kernel<<<(nIn + 255) / 256, 256>>>(dep, dep_hi, dep_lo, nIn);
    wsplit_kernel<<<1024, 256>>>(Wq, wt_hi,               wt_lo);
    wsplit_kernel<<<1024, 256>>>(Wk, wt_hi + C_ * C_,     wt_lo + C_ * C_);
    wsplit_kernel<<<1024, 256>>>(Wv, wt_hi + 2 * C_ * C_, wt_lo + 2 * C_ * C_);

    // QKV projections: [16384,512] x [512,512]^T (+bias)
    dim3 gProj(R_ / 128, C_ / 128, 1);   // (128, 4)
    gemm_bf16x3<<<gProj, 256, SMEM_B>>>(rgb_hi, rgb_lo, wt_hi, wt_lo,
        C_, 0, 0, bq, 1.f, 0, nullptr, q_hi, q_lo);
    gemm_bf16x3<<<gProj, 256, SMEM_B>>>(dep_hi, dep_lo, wt_hi + C_ * C_, wt_lo + C_ * C_,
        C_, 0, 0, bk, 1.f, 0, nullptr, k_hi, k_lo);
    gemm_bf16x3<<<gProj, 256, SMEM_B>>>(dep_hi, dep_lo, wt_hi + 2 * C_ * C_, wt_lo + 2 * C_ * C_,
        C_, 0, 0, bv, 1.f, 1, nullptr, vt_hi, vt_lo);   // V written transposed

    // Scores: per batch, S = (Q K^T) * 1/sqrt(C)
    dim3 gS(N_ / 128, M_ / 128, B_);   // (32, 32, 4)
    gemm_bf16x3<<<gS, 256, SMEM_B>>>(q_hi, q_lo, k_hi, k_lo,
        C_, (long)N_ * C_, (long)M_ * C_, nullptr, 0.044194173824159216f, 2,
        s, nullptr, nullptr);

    // Softmax rows -> P (hi/lo)
    softmax_kernel<<<R_, 256>>>(s, p_hi, p_lo);

    // Out: per batch, O = P V   (A = P K-major over m; B = V^T K-major over m)
    dim3 gO(N_ / 128, C_ / 128, B_);   // (32, 4, 4)
    gemm_bf16x3<<<gO, 256, SMEM_B>>>(p_hi, p_lo, vt_hi, vt_lo,
        M_, NM_, (long)C_ * M_, nullptr, 1.f, 3,
        out, nullptr, nullptr);
}

// round 3
// speedup vs baseline: 1.0092x; 1.0092x over previous
#include <cuda_runtime.h>
#include <cuda_bf16.h>
#include <cstdint>

// ---------------------------------------------------------------------------
// Problem constants
// ---------------------------------------------------------------------------
#define B_ 4
#define N_ 4096
#define M_ 4096
#define C_ 512
#define R_ (B_ * N_)                     // 16384 rows
static const long NM_ = (long)N_ * M_;   // 16,777,216 per batch

// ---------------------------------------------------------------------------
// GEMM tiling
// ---------------------------------------------------------------------------
#define BM 128
#define BN 128
#define BK 32
#define STAGES 3
#define ROWB 80                   // padded row bytes: 32 bf16 = 64B + 16B pad
#define TILE_B (128 * ROWB)       // 10240 B per operand tile
#define STAGE_B (4 * TILE_B)      // Ahi, Alo, Bhi, Blo
#define SMEM_B (STAGES * STAGE_B) // 122880 B

__device__ __forceinline__ uint32_t smem_u32(const void* p) {
    uint32_t a;
    asm("{ .reg .u64 t; cvta.to.shared.u64 t, %1; cvt.u32.u64 %0, t; }" : "=r"(a) : "l"(p));
    return a;
}

#define LDSM4(r, addr) \
    asm volatile("ldmatrix.sync.aligned.m8n8.x4.shared.b16 {%0,%1,%2,%3}, [%4];" \
                 : "=r"((r)[0]), "=r"((r)[1]), "=r"((r)[2]), "=r"((r)[3]) : "r"(addr))

#define MMA(dd, aa, b0, b1) \
    asm volatile("mma.sync.aligned.m16n8k16.row.col.f32.bf16.bf16.f32 " \
                 "{%0,%1,%2,%3}, {%4,%5,%6,%7}, {%8,%9}, {%0,%1,%2,%3};" \
                 : "+f"((dd)[0]), "+f"((dd)[1]), "+f"((dd)[2]), "+f"((dd)[3]) \
                 : "r"((aa)[0]), "r"((aa)[1]), "r"((aa)[2]), "r"((aa)[3]), \
                   "r"(b0), "r"(b1))

#define CP16(saddr, gptr) \
    asm volatile("cp.async.cg.shared.global [%0], [%1], 16;" :: "r"(saddr), "l"(gptr))

// ---------------------------------------------------------------------------
// Scratch (__device__ globals; no dynamic allocation allowed)
// ---------------------------------------------------------------------------
__device__ __nv_bfloat16 g_rgb_hi[R_ * C_];
__device__ __nv_bfloat16 g_rgb_lo[R_ * C_];
__device__ __nv_bfloat16 g_dep_hi[R_ * C_];
__device__ __nv_bfloat16 g_dep_lo[R_ * C_];
__device__ __nv_bfloat16 g_wt_hi[3 * C_ * C_];   // W^T for q,k,v: [co][c]
__device__ __nv_bfloat16 g_wt_lo[3 * C_ * C_];
__device__ __nv_bfloat16 g_q_hi[R_ * C_];
__device__ __nv_bfloat16 g_q_lo[R_ * C_];
__device__ __nv_bfloat16 g_k_hi[R_ * C_];
__device__ __nv_bfloat16 g_k_lo[R_ * C_];
__device__ __nv_bfloat16 g_vt_hi[(long)B_ * C_ * M_];   // V^T per batch: [b][c][m]
__device__ __nv_bfloat16 g_vt_lo[(long)B_ * C_ * M_];
__device__ __nv_bfloat16 g_p_hi[(long)B_ * N_ * M_];    // unnormalized exp hi/lo
__device__ __nv_bfloat16 g_p_lo[(long)B_ * N_ * M_];
__device__ float         g_partial[(long)R_ * 32];      // per (row, coltile) exp sums
__device__ float         g_rinv[R_];                    // 1 / rowsum

// ---------------------------------------------------------------------------
// Elementwise: fp32 -> (hi, lo) bf16 split
// ---------------------------------------------------------------------------
__global__ void split_kernel(const float* __restrict__ x,
                             __nv_bfloat16* __restrict__ hi,
                             __nv_bfloat16* __restrict__ lo, int n) {
    int i = blockIdx.x * blockDim.x + threadIdx.x;
    if (i < n) {
        float v = x[i];
        __nv_bfloat16 h = __float2bfloat16(v);
        hi[i] = h;
        lo[i] = __float2bfloat16(v - __bfloat162float(h));
    }
}

// W [c][co] -> W^T split [co][c]
__global__ void wsplit_kernel(const float* __restrict__ W,
                              __nv_bfloat16* __restrict__ hi,
                              __nv_bfloat16* __restrict__ lo) {
    int i = blockIdx.x * blockDim.x + threadIdx.x;   // i = co*512 + c
    int co = i >> 9, c = i & 511;
    float v = W[c * C_ + co];
    __nv_bfloat16 h = __float2bfloat16(v);
    hi[i] = h;
    lo[i] = __float2bfloat16(v - __bfloat162float(h));
}

// ---------------------------------------------------------------------------
// Rowsum reduce: 32 partials per row -> 1/sum
// ---------------------------------------------------------------------------
__global__ void rowsum_kernel(const float* __restrict__ partial,
                              float* __restrict__ rinv) {
    int i = blockIdx.x * blockDim.x + threadIdx.x;   // 0..R_-1
    const float4* p = (const float4*)(partial + (long)i * 32);
    float s = 0.f;
    #pragma unroll
    for (int j = 0; j < 8; j++) {
        float4 v = p[j];
        s += (v.x + v.y) + (v.z + v.w);
    }
    rinv[i] = 1.0f / s;
}

// ---------------------------------------------------------------------------
// bf16x3 GEMM via mma.sync: D[128x128] = sum_k A[rowtile,k] * B[coltile,k]
// Both operands K-major. Modes select epilogue:
//   0: out hi/lo split, row-major [row, C_], +bias[col]
//   1: out hi/lo split, transposed per batch [b][col][m], +bias[col]  (V^T)
//   2: P = exp(v*scale) hi/lo split, [bz][row][col] ld=M_, + partial row sums
//   3: out fp32 * rinv[row],  [bz][row][col] ld=C_    (final output)
// ---------------------------------------------------------------------------
__global__ void __launch_bounds__(256, 1) gemm_bf16x3(
    const __nv_bfloat16* __restrict__ Ahi, const __nv_bfloat16* __restrict__ Alo,
    const __nv_bfloat16* __restrict__ Bhi, const __nv_bfloat16* __restrict__ Blo,
    int Ktot, long aBatch, long bBatch,
    const float* __restrict__ bias, float outScale, int mode,
    float* __restrict__ outF,
    __nv_bfloat16* __restrict__ outHi, __nv_bfloat16* __restrict__ outLo,
    float* __restrict__ partial, const float* __restrict__ rinv)
{
    extern __shared__ char smem[];
    const uint32_t sb = smem_u32(smem);
    const int tid = threadIdx.x, lane = tid & 31, wid = tid >> 5;
    const int wm = wid >> 2, wn = wid & 3;          // warp grid 2 x 4
    const int bx = blockIdx.x, by = blockIdx.y, bz = blockIdx.z;

    // ---- cp.async assignment: thread -> (row, 32B half of a 64B row chunk)
    const int lrow = tid >> 1;                       // 0..127
    const int lhalf = tid & 1;                       // 0/1 -> +0B / +32B
    const long aOff = bz * aBatch + (long)(bx * 128 + lrow) * Ktot + lhalf * 16;
    const long bOff = bz * bBatch + (long)(by * 128 + lrow) * Ktot + lhalf * 16;
    const __nv_bfloat16* pAh = Ahi + aOff;
    const __nv_bfloat16* pAl = Alo + aOff;
    const __nv_bfloat16* pBh = Bhi + bOff;
    const __nv_bfloat16* pBl = Blo + bOff;
    const uint32_t sst = sb + (uint32_t)lrow * ROWB + lhalf * 32;

    const int kIters = Ktot / BK;

    auto issue = [&](int kt, int stage) {
        const uint32_t s0 = sst + stage * STAGE_B;
        const int off = kt * BK;
        CP16(s0 + 0 * TILE_B,      pAh + off);
        CP16(s0 + 0 * TILE_B + 16, pAh + off + 8);
        CP16(s0 + 1 * TILE_B,      pAl + off);
        CP16(s0 + 1 * TILE_B + 16, pAl + off + 8);
        CP16(s0 + 2 * TILE_B,      pBh + off);
        CP16(s0 + 2 * TILE_B + 16, pBh + off + 8);
        CP16(s0 + 3 * TILE_B,      pBl + off);
        CP16(s0 + 3 * TILE_B + 16, pBl + off + 8);
    };

    float d[4][4][4];
    #pragma unroll
    for (int i = 0; i < 4; i++)
        #pragma unroll
        for (int j = 0; j < 4; j++)
            #pragma unroll
            for (int e = 0; e < 4; e++) d[i][j][e] = 0.f;

    issue(0, 0);
    asm volatile("cp.async.commit_group;" ::: "memory");
    issue(1, 1);
    asm volatile("cp.async.commit_group;" ::: "memory");

    for (int kt = 0; kt < kIters; kt++) {
        asm volatile("cp.async.wait_group 1;" ::: "memory");
        __syncthreads();
        if (kt + 2 < kIters) issue(kt + 2, (kt + 2) % STAGES);
        asm volatile("cp.async.commit_group;" ::: "memory");

        const uint32_t st = sb + (kt % STAGES) * STAGE_B;
        #pragma unroll
        for (int s = 0; s < 2; s++) {                // two k16 steps per BK=32
            uint32_t ah[4][4], al[4][4], bh[4][2], bl[4][2];
            const uint32_t coff = s * 32 + (lane >> 4) * 16;
            const uint32_t rowA = wm * 64 + (lane & 15);
            #pragma unroll
            for (int mt = 0; mt < 4; mt++) {
                const uint32_t a0 = st + (rowA + mt * 16) * ROWB + coff;
                LDSM4(ah[mt], a0);
                LDSM4(al[mt], a0 + TILE_B);
            }
            const uint32_t rowB = wn * 32 + (lane & 15);
            #pragma unroll
            for (int np = 0; np < 2; np++) {
                const uint32_t b0 = st + 2 * TILE_B + (rowB + np * 16) * ROWB + coff;
                uint32_t r[4];
                LDSM4(r, b0);
                bh[2 * np][0] = r[0]; bh[2 * np][1] = r[2];
                bh[2 * np + 1][0] = r[1]; bh[2 * np + 1][1] = r[3];
                LDSM4(r, b0 + TILE_B);
                bl[2 * np][0] = r[0]; bl[2 * np][1] = r[2];
                bl[2 * np + 1][0] = r[1]; bl[2 * np + 1][1] = r[3];
            }
            #pragma unroll
            for (int mt = 0; mt < 4; mt++)
                #pragma unroll
                for (int nt = 0; nt < 4; nt++)
                    MMA(d[mt][nt], ah[mt], bh[nt][0], bh[nt][1]);   // hi*hi
            #pragma unroll
            for (int mt = 0; mt < 4; mt++)
                #pragma unroll
                for (int nt = 0; nt < 4; nt++)
                    MMA(d[mt][nt], ah[mt], bl[nt][0], bl[nt][1]);   // hi*lo
            #pragma unroll
            for (int mt = 0; mt < 4; mt++)
                #pragma unroll
                for (int nt = 0; nt < 4; nt++)
                    MMA(d[mt][nt], al[mt], bh[nt][0], bh[nt][1]);   // lo*hi
        }
    }

    // ---- epilogue (registers only; smem reused for mode-2 reduction)
    const int mbase = bx * 128 + wm * 64;
    const int nbase = by * 128 + wn * 32;
    const int lr = lane >> 2;            // 0..7
    const int lc = (lane & 3) * 2;       // 0,2,4,6

    float esum[4][2];
    #pragma unroll
    for (int i = 0; i < 4; i++) { esum[i][0] = 0.f; esum[i][1] = 0.f; }

    #pragma unroll
    for (int mt = 0; mt < 4; mt++) {
        #pragma unroll
        for (int nt = 0; nt < 4; nt++) {
            #pragma unroll
            for (int h = 0; h < 2; h++) {
                const int m = mbase + mt * 16 + lr + h * 8;
                const int n = nbase + nt * 8 + lc;
                float v0 = d[mt][nt][h * 2 + 0];
                float v1 = d[mt][nt][h * 2 + 1];
                if (mode == 0) {
                    v0 += bias[n]; v1 += bias[n + 1];
                    __nv_bfloat16 h0 = __float2bfloat16(v0);
                    __nv_bfloat16 h1 = __float2bfloat16(v1);
                    __nv_bfloat162 hv; hv.x = h0; hv.y = h1;
                    __nv_bfloat162 lv;
                    lv.x = __float2bfloat16(v0 - __bfloat162float(h0));
                    lv.y = __float2bfloat16(v1 - __bfloat162float(h1));
                    const long idx = (long)m * C_ + n;
                    *(__nv_bfloat162*)(outHi + idx) = hv;
                    *(__nv_bfloat162*)(outLo + idx) = lv;
                } else if (mode == 1) {
                    v0 += bias[n]; v1 += bias[n + 1];
                    const int b = m >> 12, mm = m & 4095;
                    const long idx = (long)b * ((long)C_ * M_) + (long)n * M_ + mm;
                    __nv_bfloat16 h0 = __float2bfloat16(v0);
                    __nv_bfloat16 h1 = __float2bfloat16(v1);
                    outHi[idx] = h0;
                    outLo[idx] = __float2bfloat16(v0 - __bfloat162float(h0));
                    outHi[idx + M_] = h1;
                    outLo[idx + M_] = __float2bfloat16(v1 - __bfloat162float(h1));
                } else if (mode == 2) {
                    float e0 = __expf(v0 * outScale);
                    float e1 = __expf(v1 * outScale);
                    esum[mt][h] += e0 + e1;
                    __nv_bfloat16 h0 = __float2bfloat16(e0);
                    __nv_bfloat16 h1 = __float2bfloat16(e1);
                    __nv_bfloat162 hv; hv.x = h0; hv.y = h1;
                    __nv_bfloat162 lv;
                    lv.x = __float2bfloat16(e0 - __bfloat162float(h0));
                    lv.y = __float2bfloat16(e1 - __bfloat162float(h1));
                    const long idx = (long)bz * NM_ + (long)m * M_ + n;
                    *(__nv_bfloat162*)(outHi + idx) = hv;
                    *(__nv_bfloat162*)(outLo + idx) = lv;
                } else {
                    const float r = rinv[bz * N_ + m];
                    const long idx = (long)bz * ((long)N_ * C_) + (long)m * C_ + n;
                    float2 v; v.x = v0 * r; v.y = v1 * r;
                    *(float2*)(outF + idx) = v;
                }
            }
        }
    }

    if (mode == 2) {
        // deterministic partial row sums: warp reduce -> smem -> global
        asm volatile("cp.async.wait_group 0;" ::: "memory");
        __syncthreads();                 // all warps done reading stage smem
        float* sred = (float*)smem;      // [4][128]
        #pragma unroll
        for (int mt = 0; mt < 4; mt++) {
            #pragma unroll
            for (int h = 0; h < 2; h++) {
                float v = esum[mt][h];
                v += __shfl_xor_sync(0xFFFFFFFFu, v, 1);
                v += __shfl_xor_sync(0xFFFFFFFFu, v, 2);
                if ((lane & 3) == 0)
                    sred[wn * 128 + wm * 64 + mt * 16 + h * 8 + lr] = v;
            }
        }
        __syncthreads();
        if (tid < 128) {
            float s = sred[tid] + sred[128 + tid] + sred[256 + tid] + sred[384 + tid];
            partial[((long)(bz * N_ + bx * 128 + tid)) * 32 + by] = s;
        }
    }
}

// ---------------------------------------------------------------------------
// Host launch
// ---------------------------------------------------------------------------
extern "C" void kernel_launch(void* const* d_in, const int* in_sizes, int n_in,
                              void* d_out, int out_size) {
    (void)in_sizes; (void)n_in; (void)out_size;
    const float* rgb = (const float*)d_in[0];
    const float* dep = (const float*)d_in[1];
    const float* Wq  = (const float*)d_in[2];
    const float* bq  = (const float*)d_in[3];
    const float* Wk  = (const float*)d_in[4];
    const float* bk  = (const float*)d_in[5];
    const float* Wv  = (const float*)d_in[6];
    const float* bv  = (const float*)d_in[7];
    float* out = (float*)d_out;

    void* p;
    __nv_bfloat16 *rgb_hi, *rgb_lo, *dep_hi, *dep_lo, *wt_hi, *wt_lo;
    __nv_bfloat16 *q_hi, *q_lo, *k_hi, *k_lo, *vt_hi, *vt_lo, *p_hi, *p_lo;
    float *partial, *rinv;
    cudaGetSymbolAddress(&p, g_rgb_hi); rgb_hi = (__nv_bfloat16*)p;
    cudaGetSymbolAddress(&p, g_rgb_lo); rgb_lo = (__nv_bfloat16*)p;
    cudaGetSymbolAddress(&p, g_dep_hi); dep_hi = (__nv_bfloat16*)p;
    cudaGetSymbolAddress(&p, g_dep_lo); dep_lo = (__nv_bfloat16*)p;
    cudaGetSymbolAddress(&p, g_wt_hi);  wt_hi  = (__nv_bfloat16*)p;
    cudaGetSymbolAddress(&p, g_wt_lo);  wt_lo  = (__nv_bfloat16*)p;
    cudaGetSymbolAddress(&p, g_q_hi);   q_hi   = (__nv_bfloat16*)p;
    cudaGetSymbolAddress(&p, g_q_lo);   q_lo   = (__nv_bfloat16*)p;
    cudaGetSymbolAddress(&p, g_k_hi);   k_hi   = (__nv_bfloat16*)p;
    cudaGetSymbolAddress(&p, g_k_lo);   k_lo   = (__nv_bfloat16*)p;
    cudaGetSymbolAddress(&p, g_vt_hi);  vt_hi  = (__nv_bfloat16*)p;
    cudaGetSymbolAddress(&p, g_vt_lo);  vt_lo  = (__nv_bfloat16*)p;
    cudaGetSymbolAddress(&p, g_p_hi);   p_hi   = (__nv_bfloat16*)p;
    cudaGetSymbolAddress(&p, g_p_lo);   p_lo   = (__nv_bfloat16*)p;
    cudaGetSymbolAddress(&p, g_partial); partial = (float*)p;
    cudaGetSymbolAddress(&p, g_rinv);    rinv    = (float*)p;

    cudaFuncSetAttribute(gemm_bf16x3, cudaFuncAttributeMaxDynamicSharedMemorySize, SMEM_B);

    const int nIn = R_ * C_;   // 8,388,608
    split_kernel<<<(nIn + 255) / 256, 256>>>(rgb, rgb_hi, rgb_lo, nIn);
    split_kernel<<<(nIn + 255) / 256, 256>>>(dep, dep_hi, dep_lo, nIn);
    wsplit_kernel<<<1024, 256>>>(Wq, wt_hi,               wt_lo);
    wsplit_kernel<<<1024, 256>>>(Wk, wt_hi + C_ * C_,     wt_lo + C_ * C_);
    wsplit_kernel<<<1024, 256>>>(Wv, wt_hi + 2 * C_ * C_, wt_lo + 2 * C_ * C_);

    // QKV projections: [16384,512] x [512,512]^T (+bias)
    dim3 gProj(R_ / 128, C_ / 128, 1);   // (128, 4)
    gemm_bf16x3<<<gProj, 256, SMEM_B>>>(rgb_hi, rgb_lo, wt_hi, wt_lo,
        C_, 0, 0, bq, 1.f, 0, nullptr, q_hi, q_lo, nullptr, nullptr);
    gemm_bf16x3<<<gProj, 256, SMEM_B>>>(dep_hi, dep_lo, wt_hi + C_ * C_, wt_lo + C_ * C_,
        C_, 0, 0, bk, 1.f, 0, nullptr, k_hi, k_lo, nullptr, nullptr);
    gemm_bf16x3<<<gProj, 256, SMEM_B>>>(dep_hi, dep_lo, wt_hi + 2 * C_ * C_, wt_lo + 2 * C_ * C_,
        C_, 0, 0, bv, 1.f, 1, nullptr, vt_hi, vt_lo, nullptr, nullptr);

    // Scores + exp fused: P = exp(Q K^T / sqrt(C)) (unnormalized), partial sums
    dim3 gS(N_ / 128, M_ / 128, B_);   // (32, 32, 4)
    gemm_bf16x3<<<gS, 256, SMEM_B>>>(q_hi, q_lo, k_hi, k_lo,
        C_, (long)N_ * C_, (long)M_ * C_, nullptr, 0.044194173824159216f, 2,
        nullptr, p_hi, p_lo, partial, nullptr);

    // rowsum -> 1/sum
    rowsum_kernel<<<R_ / 256, 256>>>(partial, rinv);

    // Out: per batch, O = (P V) * rinv[row]
    dim3 gO(N_ / 128, C_ / 128, B_);   // (32, 4, 4)
    gemm_bf16x3<<<gO, 256, SMEM_B>>>(p_hi, p_lo, vt_hi, vt_lo,
        M_, NM_, (long)C_ * M_, nullptr, 1.f, 3,
        out, nullptr, nullptr, nullptr, rinv);
}

// round 4
// speedup vs baseline: 2.4000x; 2.3782x over previous
#include <cuda_runtime.h>
#include <cuda_fp16.h>
#include <cstdint>

// ---------------------------------------------------------------------------
// Problem constants
// ---------------------------------------------------------------------------
#define B_ 4
#define N_ 4096
#define M_ 4096
#define C_ 512
#define R_ (B_ * N_)                     // 16384 rows
static const long NM_ = (long)N_ * M_;   // 16,777,216 per batch

// ---------------------------------------------------------------------------
// GEMM tiling: CTA 128x128, BK=64, fp16 single-pass, fp32 accumulate
// ---------------------------------------------------------------------------
#define BK 64
#define STAGES 3
#define ROWB 144                  // 64 fp16 = 128B + 16B pad (conflict-free)
#define TILE_B (128 * ROWB)       // 18432 B per operand tile
#define STAGE_B (2 * TILE_B)      // A, B
#define SMEM_B (STAGES * STAGE_B) // 110592 B

__device__ __forceinline__ uint32_t smem_u32(const void* p) {
    uint32_t a;
    asm("{ .reg .u64 t; cvta.to.shared.u64 t, %1; cvt.u32.u64 %0, t; }" : "=r"(a) : "l"(p));
    return a;
}

#define LDSM4(r, addr) \
    asm volatile("ldmatrix.sync.aligned.m8n8.x4.shared.b16 {%0,%1,%2,%3}, [%4];" \
                 : "=r"((r)[0]), "=r"((r)[1]), "=r"((r)[2]), "=r"((r)[3]) : "r"(addr))

#define MMA(dd, aa, b0, b1) \
    asm volatile("mma.sync.aligned.m16n8k16.row.col.f32.f16.f16.f32 " \
                 "{%0,%1,%2,%3}, {%4,%5,%6,%7}, {%8,%9}, {%0,%1,%2,%3};" \
                 : "+f"((dd)[0]), "+f"((dd)[1]), "+f"((dd)[2]), "+f"((dd)[3]) \
                 : "r"((aa)[0]), "r"((aa)[1]), "r"((aa)[2]), "r"((aa)[3]), \
                   "r"(b0), "r"(b1))

#define CP16(saddr, gptr) \
    asm volatile("cp.async.cg.shared.global [%0], [%1], 16;" :: "r"(saddr), "l"(gptr))

// ---------------------------------------------------------------------------
// Scratch (__device__ globals; no dynamic allocation allowed)
// ---------------------------------------------------------------------------
__device__ __half g_rgb[R_ * C_];
__device__ __half g_dep[R_ * C_];
__device__ __half g_wt[3 * C_ * C_];             // W^T for q,k,v: [co][c]
__device__ __half g_q[R_ * C_];
__device__ __half g_k[R_ * C_];
__device__ __half g_vt[(long)B_ * C_ * M_];      // V^T per batch: [b][c][m]
__device__ __half g_p[(long)B_ * N_ * M_];       // unnormalized exp (128 MB)
__device__ float  g_partial[(long)R_ * 32];      // per (row, coltile) exp sums
__device__ float  g_rinv[R_];                    // 1 / rowsum

// ---------------------------------------------------------------------------
// Elementwise converts
// ---------------------------------------------------------------------------
__global__ void tohalf_kernel(const float* __restrict__ x,
                              __half* __restrict__ o, int n) {
    int i = blockIdx.x * blockDim.x + threadIdx.x;
    if (i < n) o[i] = __float2half_rn(x[i]);
}

// W [c][co] -> W^T [co][c] fp16
__global__ void wT_kernel(const float* __restrict__ W, __half* __restrict__ o) {
    int i = blockIdx.x * blockDim.x + threadIdx.x;   // i = co*512 + c
    int co = i >> 9, c = i & 511;
    o[i] = __float2half_rn(W[c * C_ + co]);
}

// ---------------------------------------------------------------------------
// Rowsum reduce: 32 partials per row -> 1/sum
// ---------------------------------------------------------------------------
__global__ void rowsum_kernel(const float* __restrict__ partial,
                              float* __restrict__ rinv) {
    int i = blockIdx.x * blockDim.x + threadIdx.x;   // 0..R_-1
    const float4* p = (const float4*)(partial + (long)i * 32);
    float s = 0.f;
    #pragma unroll
    for (int j = 0; j < 8; j++) {
        float4 v = p[j];
        s += (v.x + v.y) + (v.z + v.w);
    }
    rinv[i] = 1.0f / s;
}

// ---------------------------------------------------------------------------
// fp16 GEMM via mma.sync: D[128x128] = sum_k A[rowtile,k] * B[coltile,k]
// Both operands K-major. Modes select epilogue:
//   0: out fp16, row-major [row, C_], +bias[col]
//   1: out fp16, transposed per batch [b][col][m], +bias[col]  (V^T)
//   2: P = exp(v*scale) fp16, [bz][row][col] ld=M_, + partial row sums
//   3: out fp32 * rinv[row],  [bz][row][col] ld=C_    (final output)
// ---------------------------------------------------------------------------
__global__ void __launch_bounds__(256, 2) gemm_f16(
    const __half* __restrict__ A, const __half* __restrict__ Bp,
    int Ktot, long aBatch, long bBatch,
    const float* __restrict__ bias, float outScale, int mode,
    float* __restrict__ outF, __half* __restrict__ outH,
    float* __restrict__ partial, const float* __restrict__ rinv)
{
    extern __shared__ char smem[];
    const uint32_t sb = smem_u32(smem);
    const int tid = threadIdx.x, lane = tid & 31, wid = tid >> 5;
    const int wm = wid >> 2, wn = wid & 3;          // warp grid 2 x 4
    const int bx = blockIdx.x, by = blockIdx.y, bz = blockIdx.z;

    // ---- cp.async assignment: thread -> (row, 64B half of a 128B row)
    const int lrow = tid >> 1;                       // 0..127
    const int lhalf = tid & 1;                       // 0/1 -> +0B / +64B
    const __half* pA = A  + bz * aBatch + (long)(bx * 128 + lrow) * Ktot + lhalf * 32;
    const __half* pB = Bp + bz * bBatch + (long)(by * 128 + lrow) * Ktot + lhalf * 32;
    const uint32_t sst = sb + (uint32_t)lrow * ROWB + lhalf * 64;

    const int kIters = Ktot / BK;

    auto issue = [&](int kt, int stage) {
        const uint32_t s0 = sst + stage * STAGE_B;
        const int off = kt * BK;
        #pragma unroll
        for (int c = 0; c < 4; c++) {
            CP16(s0 + c * 16,          pA + off + c * 8);
            CP16(s0 + TILE_B + c * 16, pB + off + c * 8);
        }
    };

    float d[4][4][4];
    #pragma unroll
    for (int i = 0; i < 4; i++)
        #pragma unroll
        for (int j = 0; j < 4; j++)
            #pragma unroll
            for (int e = 0; e < 4; e++) d[i][j][e] = 0.f;

    issue(0, 0);
    asm volatile("cp.async.commit_group;" ::: "memory");
    issue(1, 1);
    asm volatile("cp.async.commit_group;" ::: "memory");

    for (int kt = 0; kt < kIters; kt++) {
        asm volatile("cp.async.wait_group 1;" ::: "memory");
        __syncthreads();
        if (kt + 2 < kIters) issue(kt + 2, (kt + 2) % STAGES);
        asm volatile("cp.async.commit_group;" ::: "memory");

        const uint32_t st = sb + (kt % STAGES) * STAGE_B;
        #pragma unroll
        for (int s = 0; s < 4; s++) {                // four k16 steps per BK=64
            uint32_t ah[4][4], bh[4][2];
            const uint32_t coff = s * 32 + (lane >> 4) * 16;
            const uint32_t rowA = wm * 64 + (lane & 15);
            #pragma unroll
            for (int mt = 0; mt < 4; mt++)
                LDSM4(ah[mt], st + (rowA + mt * 16) * ROWB + coff);
            const uint32_t rowB = wn * 32 + (lane & 15);
            #pragma unroll
            for (int np = 0; np < 2; np++) {
                uint32_t r[4];
                LDSM4(r, st + TILE_B + (rowB + np * 16) * ROWB + coff);
                bh[2 * np][0] = r[0]; bh[2 * np][1] = r[2];
                bh[2 * np + 1][0] = r[1]; bh[2 * np + 1][1] = r[3];
            }
            #pragma unroll
            for (int mt = 0; mt < 4; mt++)
                #pragma unroll
                for (int nt = 0; nt < 4; nt++)
                    MMA(d[mt][nt], ah[mt], bh[nt][0], bh[nt][1]);
        }
    }

    // ---- epilogue (registers only; smem reused for mode-2 reduction)
    const int mbase = bx * 128 + wm * 64;
    const int nbase = by * 128 + wn * 32;
    const int lr = lane >> 2;            // 0..7
    const int lc = (lane & 3) * 2;       // 0,2,4,6

    float esum[4][2];
    #pragma unroll
    for (int i = 0; i < 4; i++) { esum[i][0] = 0.f; esum[i][1] = 0.f; }

    #pragma unroll
    for (int mt = 0; mt < 4; mt++) {
        #pragma unroll
        for (int nt = 0; nt < 4; nt++) {
            #pragma unroll
            for (int h = 0; h < 2; h++) {
                const int m = mbase + mt * 16 + lr + h * 8;
                const int n = nbase + nt * 8 + lc;
                float v0 = d[mt][nt][h * 2 + 0];
                float v1 = d[mt][nt][h * 2 + 1];
                if (mode == 0) {
                    v0 += bias[n]; v1 += bias[n + 1];
                    __half2 hv;
                    hv.x = __float2half_rn(v0); hv.y = __float2half_rn(v1);
                    *(__half2*)(outH + (long)m * C_ + n) = hv;
                } else if (mode == 1) {
                    v0 += bias[n]; v1 += bias[n + 1];
                    const int b = m >> 12, mm = m & 4095;
                    const long idx = (long)b * ((long)C_ * M_) + (long)n * M_ + mm;
                    outH[idx]      = __float2half_rn(v0);
                    outH[idx + M_] = __float2half_rn(v1);
                } else if (mode == 2) {
                    float e0 = __expf(v0 * outScale);
                    float e1 = __expf(v1 * outScale);
                    esum[mt][h] += e0 + e1;
                    __half2 hv;
                    hv.x = __float2half_rn(e0); hv.y = __float2half_rn(e1);
                    *(__half2*)(outH + (long)bz * NM_ + (long)m * M_ + n) = hv;
                } else {
                    const float r = rinv[bz * N_ + m];
                    const long idx = (long)bz * ((long)N_ * C_) + (long)m * C_ + n;
                    float2 v; v.x = v0 * r; v.y = v1 * r;
                    *(float2*)(outF + idx) = v;
                }
            }
        }
    }

    if (mode == 2) {
        // deterministic partial row sums: warp reduce -> smem -> global
        asm volatile("cp.async.wait_group 0;" ::: "memory");
        __syncthreads();                 // all warps done with stage smem
        float* sred = (float*)smem;      // [4][128]
        #pragma unroll
        for (int mt = 0; mt < 4; mt++) {
            #pragma unroll
            for (int h = 0; h < 2; h++) {
                float v = esum[mt][h];
                v += __shfl_xor_sync(0xFFFFFFFFu, v, 1);
                v += __shfl_xor_sync(0xFFFFFFFFu, v, 2);
                if ((lane & 3) == 0)
                    sred[wn * 128 + wm * 64 + mt * 16 + h * 8 + lr] = v;
            }
        }
        __syncthreads();
        if (tid < 128) {
            float s = sred[tid] + sred[128 + tid] + sred[256 + tid] + sred[384 + tid];
            partial[((long)(bz * N_ + bx * 128 + tid)) * 32 + by] = s;
        }
    }
}

// ---------------------------------------------------------------------------
// Host launch
// ---------------------------------------------------------------------------
extern "C" void kernel_launch(void* const* d_in, const int* in_sizes, int n_in,
                              void* d_out, int out_size) {
    (void)in_sizes; (void)n_in; (void)out_size;
    const float* rgb = (const float*)d_in[0];
    const float* dep = (const float*)d_in[1];
    const float* Wq  = (const float*)d_in[2];
    const float* bq  = (const float*)d_in[3];
    const float* Wk  = (const float*)d_in[4];
    const float* bk  = (const float*)d_in[5];
    const float* Wv  = (const float*)d_in[6];
    const float* bv  = (const float*)d_in[7];
    float* out = (float*)d_out;

    void* p;
    __half *rgb_h, *dep_h, *wt, *q, *k, *vt, *ph;
    float *partial, *rinv;
    cudaGetSymbolAddress(&p, g_rgb);     rgb_h   = (__half*)p;
    cudaGetSymbolAddress(&p, g_dep);     dep_h   = (__half*)p;
    cudaGetSymbolAddress(&p, g_wt);      wt      = (__half*)p;
    cudaGetSymbolAddress(&p, g_q);       q       = (__half*)p;
    cudaGetSymbolAddress(&p, g_k);       k       = (__half*)p;
    cudaGetSymbolAddress(&p, g_vt);      vt      = (__half*)p;
    cudaGetSymbolAddress(&p, g_p);       ph      = (__half*)p;
    cudaGetSymbolAddress(&p, g_partial); partial = (float*)p;
    cudaGetSymbolAddress(&p, g_rinv);    rinv    = (float*)p;

    cudaFuncSetAttribute(gemm_f16, cudaFuncAttributeMaxDynamicSharedMemorySize, SMEM_B);

    const int nIn = R_ * C_;   // 8,388,608
    tohalf_kernel<<<(nIn + 255) / 256, 256>>>(rgb, rgb_h, nIn);
    tohalf_kernel<<<(nIn + 255) / 256, 256>>>(dep, dep_h, nIn);
    wT_kernel<<<1024, 256>>>(Wq, wt);
    wT_kernel<<<1024, 256>>>(Wk, wt + C_ * C_);
    wT_kernel<<<1024, 256>>>(Wv, wt + 2 * C_ * C_);

    // QKV projections: [16384,512] x [512,512]^T (+bias)
    dim3 gProj(R_ / 128, C_ / 128, 1);   // (128, 4)
    gemm_f16<<<gProj, 256, SMEM_B>>>(rgb_h, wt,
        C_, 0, 0, bq, 1.f, 0, nullptr, q, nullptr, nullptr);
    gemm_f16<<<gProj, 256, SMEM_B>>>(dep_h, wt + C_ * C_,
        C_, 0, 0, bk, 1.f, 0, nullptr, k, nullptr, nullptr);
    gemm_f16<<<gProj, 256, SMEM_B>>>(dep_h, wt + 2 * C_ * C_,
        C_, 0, 0, bv, 1.f, 1, nullptr, vt, nullptr, nullptr);   // V^T

    // Scores + exp fused: P = exp(Q K^T / sqrt(C)) (unnormalized) + partials
    dim3 gS(N_ / 128, M_ / 128, B_);   // (32, 32, 4)
    gemm_f16<<<gS, 256, SMEM_B>>>(q, k,
        C_, (long)N_ * C_, (long)M_ * C_, nullptr, 0.044194173824159216f, 2,
        nullptr, ph, partial, nullptr);

    // rowsum -> 1/sum
    rowsum_kernel<<<R_ / 256, 256>>>(partial, rinv);

    // Out: per batch, O = (P V) * rinv[row]
    dim3 gO(N_ / 128, C_ / 128, B_);   // (32, 4, 4)
    gemm_f16<<<gO, 256, SMEM_B>>>(ph, vt,
        M_, NM_, (long)C_ * M_, nullptr, 1.f, 3,
        out, nullptr, nullptr, rinv);
}

// round 7
// speedup vs baseline: 2.4924x; 1.0385x over previous
#include <cuda_runtime.h>
#include <cuda_fp16.h>
#include <cstdint>

// ---------------------------------------------------------------------------
// Problem constants
// ---------------------------------------------------------------------------
#define B_ 4
#define N_ 4096
#define M_ 4096
#define C_ 512
#define R_ (B_ * N_)                     // 16384 rows
static const long NM_ = (long)N_ * M_;   // 16,777,216 per batch

// ---------------------------------------------------------------------------
// GEMM tiling: CTA 128x128, BK=64, fp16 single-pass, fp32 accumulate
// ---------------------------------------------------------------------------
#define BK 64
#define STAGES 3
#define ROWB 144                  // 64 fp16 = 128B + 16B pad (conflict-free)
#define TILE_B (128 * ROWB)       // 18432 B per operand tile
#define STAGE_B (2 * TILE_B)      // A, B
#define SMEM_B (STAGES * STAGE_B) // 110592 B

__device__ __forceinline__ uint32_t smem_u32(const void* p) {
    uint32_t a;
    asm("{ .reg .u64 t; cvta.to.shared.u64 t, %1; cvt.u32.u64 %0, t; }" : "=r"(a) : "l"(p));
    return a;
}

#define LDSM4(r, addr) \
    asm volatile("ldmatrix.sync.aligned.m8n8.x4.shared.b16 {%0,%1,%2,%3}, [%4];" \
                 : "=r"((r)[0]), "=r"((r)[1]), "=r"((r)[2]), "=r"((r)[3]) : "r"(addr))

#define MMA(dd, aa, b0, b1) \
    asm volatile("mma.sync.aligned.m16n8k16.row.col.f32.f16.f16.f32 " \
                 "{%0,%1,%2,%3}, {%4,%5,%6,%7}, {%8,%9}, {%0,%1,%2,%3};" \
                 : "+f"((dd)[0]), "+f"((dd)[1]), "+f"((dd)[2]), "+f"((dd)[3]) \
                 : "r"((aa)[0]), "r"((aa)[1]), "r"((aa)[2]), "r"((aa)[3]), \
                   "r"(b0), "r"(b1))

#define CP16(saddr, gptr) \
    asm volatile("cp.async.cg.shared.global [%0], [%1], 16;" :: "r"(saddr), "l"(gptr))

// ---------------------------------------------------------------------------
// Scratch (__device__ globals; no dynamic allocation allowed)
// ---------------------------------------------------------------------------
__device__ __half g_rgb[R_ * C_];
__device__ __half g_dep[R_ * C_];
__device__ __half g_wt[3 * C_ * C_];             // W^T for q,k,v: [co][c]
__device__ __half g_q[R_ * C_];
__device__ __half g_k[R_ * C_];
__device__ __half g_vt[(long)B_ * C_ * M_];      // V^T per batch: [b][c][m]
__device__ __half g_p[(long)B_ * N_ * M_];       // unnormalized exp (128 MB)
__device__ float  g_partial[(long)R_ * 32];      // per (row, coltile) exp sums
__device__ float  g_rinv[R_];                    // 1 / rowsum

// ---------------------------------------------------------------------------
// ONE conversion kernel: rgb->fp16, dep->fp16, Wq/Wk/Wv -> W^T fp16.
// Vectorized float4 path for the two big inputs; scalar transpose for W.
// Launch: grid covers (2*nIn)/4 + 3*C*C work items.
// ---------------------------------------------------------------------------
#define NIN (R_ * C_)                    // 8,388,608
#define NV4 (NIN / 4)                    // float4 chunks per input
#define WCNT (C_ * C_)                   // 262,144 per weight

__global__ void __launch_bounds__(256) convert_all(
    const float* __restrict__ rgb, const float* __restrict__ dep,
    const float* __restrict__ Wq, const float* __restrict__ Wk,
    const float* __restrict__ Wv,
    __half* __restrict__ orgb, __half* __restrict__ odep,
    __half* __restrict__ owt)
{
    int i = blockIdx.x * blockDim.x + threadIdx.x;
    if (i < 2 * NV4) {
        const float4* src = (i < NV4) ? (const float4*)rgb : (const float4*)dep;
        __half* dst = (i < NV4) ? orgb : odep;
        int j = (i < NV4) ? i : i - NV4;
        float4 v = src[j];
        __half2 h0, h1;
        h0.x = __float2half_rn(v.x); h0.y = __float2half_rn(v.y);
        h1.x = __float2half_rn(v.z); h1.y = __float2half_rn(v.w);
        *(__half2*)(dst + j * 4)     = h0;
        *(__half2*)(dst + j * 4 + 2) = h1;
    } else {
        int j = i - 2 * NV4;               // 0 .. 3*WCNT-1
        if (j < 3 * WCNT) {
            const float* W = (j < WCNT) ? Wq : (j < 2 * WCNT) ? Wk : Wv;
            int t = (j < WCNT) ? j : (j < 2 * WCNT) ? j - WCNT : j - 2 * WCNT;
            int co = t >> 9, c = t & 511;
            owt[j] = __float2half_rn(W[c * C_ + co]);
        }
    }
}

// ---------------------------------------------------------------------------
// Rowsum reduce: 32 partials per row -> 1/sum
// ---------------------------------------------------------------------------
__global__ void rowsum_kernel(const float* __restrict__ partial,
                              float* __restrict__ rinv) {
    int i = blockIdx.x * blockDim.x + threadIdx.x;   // 0..R_-1
    const float4* p = (const float4*)(partial + (long)i * 32);
    float s = 0.f;
    #pragma unroll
    for (int j = 0; j < 8; j++) {
        float4 v = p[j];
        s += (v.x + v.y) + (v.z + v.w);
    }
    rinv[i] = 1.0f / s;
}

// ---------------------------------------------------------------------------
// fp16 GEMM via mma.sync: D[128x128] = sum_k A[rowtile,k] * B[coltile,k]
// Both operands K-major. Modes select epilogue:
//   0: out fp16, row-major [row, C_], +bias[col]
//   1: out fp16, transposed per batch [b][col][m], +bias[col]  (V^T)
//   2: P = exp(v*scale) fp16, [bz][row][col] ld=M_, + partial row sums
//   3: out fp32 * rinv[row],  [bz][row][col] ld=C_    (final output)
// ---------------------------------------------------------------------------
__global__ void __launch_bounds__(256, 2) gemm_f16(
    const __half* __restrict__ A, const __half* __restrict__ Bp,
    int Ktot, long aBatch, long bBatch,
    const float* __restrict__ bias, float outScale, int mode,
    float* __restrict__ outF, __half* __restrict__ outH,
    float* __restrict__ partial, const float* __restrict__ rinv)
{
    extern __shared__ char smem[];
    const uint32_t sb = smem_u32(smem);
    const int tid = threadIdx.x, lane = tid & 31, wid = tid >> 5;
    const int wm = wid >> 2, wn = wid & 3;          // warp grid 2 x 4
    const int bx = blockIdx.x, by = blockIdx.y, bz = blockIdx.z;

    // ---- cp.async assignment: thread -> (row, 64B half of a 128B row)
    const int lrow = tid >> 1;                       // 0..127
    const int lhalf = tid & 1;                       // 0/1 -> +0B / +64B
    const __half* pA = A  + bz * aBatch + (long)(bx * 128 + lrow) * Ktot + lhalf * 32;
    const __half* pB = Bp + bz * bBatch + (long)(by * 128 + lrow) * Ktot + lhalf * 32;
    const uint32_t sst = sb + (uint32_t)lrow * ROWB + lhalf * 64;

    const int kIters = Ktot / BK;

    auto issue = [&](int kt, int stage) {
        const uint32_t s0 = sst + stage * STAGE_B;
        const int off = kt * BK;
        #pragma unroll
        for (int c = 0; c < 4; c++) {
            CP16(s0 + c * 16,          pA + off + c * 8);
            CP16(s0 + TILE_B + c * 16, pB + off + c * 8);
        }
    };

    float d[4][4][4];
    #pragma unroll
    for (int i = 0; i < 4; i++)
        #pragma unroll
        for (int j = 0; j < 4; j++)
            #pragma unroll
            for (int e = 0; e < 4; e++) d[i][j][e] = 0.f;

    issue(0, 0);
    asm volatile("cp.async.commit_group;" ::: "memory");
    issue(1, 1);
    asm volatile("cp.async.commit_group;" ::: "memory");

    for (int kt = 0; kt < kIters; kt++) {
        asm volatile("cp.async.wait_group 1;" ::: "memory");
        __syncthreads();
        if (kt + 2 < kIters) issue(kt + 2, (kt + 2) % STAGES);
        asm volatile("cp.async.commit_group;" ::: "memory");

        const uint32_t st = sb + (kt % STAGES) * STAGE_B;
        #pragma unroll
        for (int s = 0; s < 4; s++) {                // four k16 steps per BK=64
            uint32_t ah[4][4], bh[4][2];
            const uint32_t coff = s * 32 + (lane >> 4) * 16;
            const uint32_t rowA = wm * 64 + (lane & 15);
            #pragma unroll
            for (int mt = 0; mt < 4; mt++)
                LDSM4(ah[mt], st + (rowA + mt * 16) * ROWB + coff);
            const uint32_t rowB = wn * 32 + (lane & 15);
            #pragma unroll
            for (int np = 0; np < 2; np++) {
                uint32_t r[4];
                LDSM4(r, st + TILE_B + (rowB + np * 16) * ROWB + coff);
                bh[2 * np][0] = r[0]; bh[2 * np][1] = r[2];
                bh[2 * np + 1][0] = r[1]; bh[2 * np + 1][1] = r[3];
            }
            #pragma unroll
            for (int mt = 0; mt < 4; mt++)
                #pragma unroll
                for (int nt = 0; nt < 4; nt++)
                    MMA(d[mt][nt], ah[mt], bh[nt][0], bh[nt][1]);
        }
    }

    // ---- epilogue (registers only; smem reused for mode-2 reduction)
    const int mbase = bx * 128 + wm * 64;
    const int nbase = by * 128 + wn * 32;
    const int lr = lane >> 2;            // 0..7
    const int lc = (lane & 3) * 2;       // 0,2,4,6

    float esum[4][2];
    #pragma unroll
    for (int i = 0; i < 4; i++) { esum[i][0] = 0.f; esum[i][1] = 0.f; }

    #pragma unroll
    for (int mt = 0; mt < 4; mt++) {
        #pragma unroll
        for (int nt = 0; nt < 4; nt++) {
            #pragma unroll
            for (int h = 0; h < 2; h++) {
                const int m = mbase + mt * 16 + lr + h * 8;
                const int n = nbase + nt * 8 + lc;
                float v0 = d[mt][nt][h * 2 + 0];
                float v1 = d[mt][nt][h * 2 + 1];
                if (mode == 0) {
                    v0 += bias[n]; v1 += bias[n + 1];
                    __half2 hv;
                    hv.x = __float2half_rn(v0); hv.y = __float2half_rn(v1);
                    *(__half2*)(outH + (long)m * C_ + n) = hv;
                } else if (mode == 1) {
                    v0 += bias[n]; v1 += bias[n + 1];
                    const int b = m >> 12, mm = m & 4095;
                    const long idx = (long)b * ((long)C_ * M_) + (long)n * M_ + mm;
                    outH[idx]      = __float2half_rn(v0);
                    outH[idx + M_] = __float2half_rn(v1);
                } else if (mode == 2) {
                    float e0 = __expf(v0 * outScale);
                    float e1 = __expf(v1 * outScale);
                    esum[mt][h] += e0 + e1;
                    __half2 hv;
                    hv.x = __float2half_rn(e0); hv.y = __float2half_rn(e1);
                    *(__half2*)(outH + (long)bz * NM_ + (long)m * M_ + n) = hv;
                } else {
                    const float r = rinv[bz * N_ + m];
                    const long idx = (long)bz * ((long)N_ * C_) + (long)m * C_ + n;
                    float2 v; v.x = v0 * r; v.y = v1 * r;
                    *(float2*)(outF + idx) = v;
                }
            }
        }
    }

    if (mode == 2) {
        // deterministic partial row sums: warp reduce -> smem -> global
        asm volatile("cp.async.wait_group 0;" ::: "memory");
        __syncthreads();                 // all warps done with stage smem
        float* sred = (float*)smem;      // [4][128]
        #pragma unroll
        for (int mt = 0; mt < 4; mt++) {
            #pragma unroll
            for (int h = 0; h < 2; h++) {
                float v = esum[mt][h];
                v += __shfl_xor_sync(0xFFFFFFFFu, v, 1);
                v += __shfl_xor_sync(0xFFFFFFFFu, v, 2);
                if ((lane & 3) == 0)
                    sred[wn * 128 + wm * 64 + mt * 16 + h * 8 + lr] = v;
            }
        }
        __syncthreads();
        if (tid < 128) {
            float s = sred[tid] + sred[128 + tid] + sred[256 + tid] + sred[384 + tid];
            partial[((long)(bz * N_ + bx * 128 + tid)) * 32 + by] = s;
        }
    }
}

// ---------------------------------------------------------------------------
// Host launch.  Order matters for ncu (-s 5 -c 1 captures the 5th launch):
//   1 convert_all, 2 projQ, 3 projK, 4 projV, 5 SCORES GEMM, 6 rowsum, 7 PV
// ---------------------------------------------------------------------------
extern "C" void kernel_launch(void* const* d_in, const int* in_sizes, int n_in,
                              void* d_out, int out_size) {
    (void)in_sizes; (void)n_in; (void)out_size;
    const float* rgb = (const float*)d_in[0];
    const float* dep = (const float*)d_in[1];
    const float* Wq  = (const float*)d_in[2];
    const float* bq  = (const float*)d_in[3];
    const float* Wk  = (const float*)d_in[4];
    const float* bk  = (const float*)d_in[5];
    const float* Wv  = (const float*)d_in[6];
    const float* bv  = (const float*)d_in[7];
    float* out = (float*)d_out;

    void* p;
    __half *rgb_h, *dep_h, *wt, *q, *k, *vt, *ph;
    float *partial, *rinv;
    cudaGetSymbolAddress(&p, g_rgb);     rgb_h   = (__half*)p;
    cudaGetSymbolAddress(&p, g_dep);     dep_h   = (__half*)p;
    cudaGetSymbolAddress(&p, g_wt);      wt      = (__half*)p;
    cudaGetSymbolAddress(&p, g_q);       q       = (__half*)p;
    cudaGetSymbolAddress(&p, g_k);       k       = (__half*)p;
    cudaGetSymbolAddress(&p, g_vt);      vt      = (__half*)p;
    cudaGetSymbolAddress(&p, g_p);       ph      = (__half*)p;
    cudaGetSymbolAddress(&p, g_partial); partial = (float*)p;
    cudaGetSymbolAddress(&p, g_rinv);    rinv    = (float*)p;

    cudaFuncSetAttribute(gemm_f16, cudaFuncAttributeMaxDynamicSharedMemorySize, SMEM_B);

    // Launch 1: all conversions in one kernel
    const int workItems = 2 * NV4 + 3 * WCNT;     // 4,980,736
    convert_all<<<(workItems + 255) / 256, 256>>>(rgb, dep, Wq, Wk, Wv,
                                                  rgb_h, dep_h, wt);

    // Launches 2-4: QKV projections  [16384,512] x [512,512]^T (+bias)
    dim3 gProj(R_ / 128, C_ / 128, 1);   // (128, 4)
    gemm_f16<<<gProj, 256, SMEM_B>>>(rgb_h, wt,
        C_, 0, 0, bq, 1.f, 0, nullptr, q, nullptr, nullptr);
    gemm_f16<<<gProj, 256, SMEM_B>>>(dep_h, wt + C_ * C_,
        C_, 0, 0, bk, 1.f, 0, nullptr, k, nullptr, nullptr);
    gemm_f16<<<gProj, 256, SMEM_B>>>(dep_h, wt + 2 * C_ * C_,
        C_, 0, 0, bv, 1.f, 1, nullptr, vt, nullptr, nullptr);   // V^T

    // Launch 5 (ncu target): scores + exp fused
    dim3 gS(N_ / 128, M_ / 128, B_);   // (32, 32, 4)
    gemm_f16<<<gS, 256, SMEM_B>>>(q, k,
        C_, (long)N_ * C_, (long)M_ * C_, nullptr, 0.044194173824159216f, 2,
        nullptr, ph, partial, nullptr);

    // Launch 6: rowsum -> 1/sum
    rowsum_kernel<<<R_ / 256, 256>>>(partial, rinv);

    // Launch 7: O = (P V) * rinv[row]
    dim3 gO(N_ / 128, C_ / 128, B_);   // (32, 4, 4)
    gemm_f16<<<gO, 256, SMEM_B>>>(ph, vt,
        M_, NM_, (long)C_ * M_, nullptr, 1.f, 3,
        out, nullptr, nullptr, rinv);
}